// round 13
// baseline (speedup 1.0000x reference)
#include <cuda_runtime.h>
#include <cfloat>
#include <math.h>

#define Bn 64
#define Dn 256
#define Ln 4096
#define DKn 128
#define LN_EPS 1e-6f
#define EPS_CLIP 1e-10f

#define CH1 64                 // l-chunk per block
#define NCH (Ln / CH1)         // 64 chunks per batch

// ---------------- scratch (static device globals; no allocation) ----------------
__device__ float g_mu[Bn * Ln];
__device__ float g_rsig[Bn * Ln];
__device__ float g_PU[Bn * NCH * 3 * Dn];   // pass1 per-chunk partials U1,U2,U3
__device__ float g_PR[Bn * NCH * 3 * Dn];   // fused per-chunk partials R1,R2,R3 (unnormalized)
__device__ float g_U1[Bn * Dn], g_U2[Bn * Dn], g_U3[Bn * Dn];
__device__ float g_R1[Bn * Dn], g_R2[Bn * Dn], g_R3[Bn * Dn];  // scaled (flash), unnormalized
__device__ float g_Psmr[Bn * NCH];
__device__ float g_Ps22[Bn * NCH];
__device__ float g_Pml[Bn * NCH];           // chunk-local score max
__device__ float g_Pse[Bn * NCH];           // sum of e
__device__ float g_Pa[Bn * NCH];            // sum of e*mu*rsig
__device__ float g_Pm2[Bn * NCH];           // sum of e*(mu*rsig)^2
__device__ float g_gp[Bn * Dn];
__device__ float g_corr[Bn * Dn];
__device__ float g_Cb[Bn], g_Gp[Bn];

// ---------------- reduction helpers ----------------
__device__ __forceinline__ float warpSum(float v) {
#pragma unroll
    for (int o = 16; o; o >>= 1) v += __shfl_xor_sync(0xffffffffu, v, o);
    return v;
}
__device__ __forceinline__ float warpMax(float v) {
#pragma unroll
    for (int o = 16; o; o >>= 1) v = fmaxf(v, __shfl_xor_sync(0xffffffffu, v, o));
    return v;
}
__device__ __forceinline__ float bSum(float v) {
    __shared__ float sh[32];
    int lane = threadIdx.x & 31, w = threadIdx.x >> 5;
    int nw = (blockDim.x + 31) >> 5;
    v = warpSum(v);
    if (lane == 0) sh[w] = v;
    __syncthreads();
    if (w == 0) {
        float x = (lane < nw) ? sh[lane] : 0.0f;
        x = warpSum(x);
        if (lane == 0) sh[0] = x;
    }
    __syncthreads();
    float r = sh[0];
    __syncthreads();
    return r;
}

// ---------------- 1. fused LN stats + U-partials; phase B re-reads v from L2 ----------------
// __launch_bounds__(512, 3): cap regs at 42 to force 3 blocks/SM.
__global__ void __launch_bounds__(512, 3) k_pass1(const float* __restrict__ v) {
    __shared__ float s_mu[CH1], s_rs[CH1], s_mr[CH1], s_m2[CH1];
    __shared__ float sA[64 * 33];
    __shared__ float sQ[64 * 33];

    int t = threadIdx.x;                    // 512
    int b = blockIdx.x >> 6;                // NCH == 64
    int ch = blockIdx.x & 63;
    int l0 = ch * CH1;
    int bc = blockIdx.x;
    int dg = t >> 4;                        // 0..31
    int lv = t & 15;

    const float* vbase = v + (size_t)b * Dn * Ln + l0 + lv * 4;
    float cs0 = 0.f, cs1 = 0.f, cs2 = 0.f, cs3 = 0.f;
    float cq0 = 0.f, cq1 = 0.f, cq2 = 0.f, cq3 = 0.f;
#pragma unroll
    for (int it = 0; it < 8; it++) {
        int d = it * 32 + dg;
        float4 x = *reinterpret_cast<const float4*>(vbase + (size_t)d * Ln);
        cs0 += x.x; cs1 += x.y; cs2 += x.z; cs3 += x.w;
        cq0 = fmaf(x.x, x.x, cq0);
        cq1 = fmaf(x.y, x.y, cq1);
        cq2 = fmaf(x.z, x.z, cq2);
        cq3 = fmaf(x.w, x.w, cq3);
    }
    sA[(lv * 4 + 0) * 33 + dg] = cs0;
    sA[(lv * 4 + 1) * 33 + dg] = cs1;
    sA[(lv * 4 + 2) * 33 + dg] = cs2;
    sA[(lv * 4 + 3) * 33 + dg] = cs3;
    sQ[(lv * 4 + 0) * 33 + dg] = cq0;
    sQ[(lv * 4 + 1) * 33 + dg] = cq1;
    sQ[(lv * 4 + 2) * 33 + dg] = cq2;
    sQ[(lv * 4 + 3) * 33 + dg] = cq3;
    __syncthreads();

    if (t < CH1) {
        float ss = 0.f, qq = 0.f;
#pragma unroll
        for (int g = 0; g < 32; g++) {
            ss += sA[t * 33 + g];
            qq += sQ[t * 33 + g];
        }
        float mu = ss * (1.0f / Dn);
        float var = qq * (1.0f / Dn) - mu * mu;
        float rs = rsqrtf(var + LN_EPS);
        s_mu[t] = mu;
        s_rs[t] = rs;
        g_mu[b * Ln + l0 + t] = mu;
        g_rsig[b * Ln + l0 + t] = rs;
        float mr = mu * rs;
        s_mr[t] = mr;
        s_m2[t] = mr * mr;
    }
    __syncthreads();

    if (t < 32) {
        float a = s_mr[t] + s_mr[32 + t];
        a = warpSum(a);
        if (t == 0) g_Psmr[bc] = a;
    } else if (t < 64) {
        int u = t - 32;
        float a = s_m2[u] + s_m2[32 + u];
        a = warpSum(a);
        if (u == 0) g_Ps22[bc] = a;
    }

    float r0 = s_rs[lv * 4 + 0], r1 = s_rs[lv * 4 + 1], r2 = s_rs[lv * 4 + 2], r3 = s_rs[lv * 4 + 3];
    float am0 = s_mu[lv * 4 + 0] * r0 * r0;
    float am1 = s_mu[lv * 4 + 1] * r1 * r1;
    float am2 = s_mu[lv * 4 + 2] * r2 * r2;
    float am3 = s_mu[lv * 4 + 3] * r3 * r3;

    // Phase B: re-read v (L2-hot)
#pragma unroll
    for (int it = 0; it < 8; it++) {
        int d = it * 32 + dg;
        float4 xx = *reinterpret_cast<const float4*>(vbase + (size_t)d * Ln);
        float xr0 = xx.x * r0, xr1 = xx.y * r1, xr2 = xx.z * r2, xr3 = xx.w * r3;
        float u1 = (xr0 + xr1) + (xr2 + xr3);
        float u2 = fmaf(xr0, xr0, fmaf(xr1, xr1, fmaf(xr2, xr2, xr3 * xr3)));
        float u3 = fmaf(xx.x, am0, fmaf(xx.y, am1, fmaf(xx.z, am2, xx.w * am3)));
#pragma unroll
        for (int o = 8; o; o >>= 1) {
            u1 += __shfl_down_sync(0xffffffffu, u1, o);
            u2 += __shfl_down_sync(0xffffffffu, u2, o);
            u3 += __shfl_down_sync(0xffffffffu, u3, o);
        }
        if (lv == 0) {
            g_PU[(bc * 3 + 0) * Dn + d] = u1;
            g_PU[(bc * 3 + 1) * Dn + d] = u2;
            g_PU[(bc * 3 + 2) * Dn + d] = u3;
        }
    }
}

// ---------------- 1b. wide-grid combine of U partials ----------------
__global__ void __launch_bounds__(512) k_combineU() {
    __shared__ float sred[3 * 512];
    int b = blockIdx.x >> 2;
    int d0 = (blockIdx.x & 3) * 64;
    int t = threadIdx.x;
    int dl = t & 63, cs = t >> 6;
    int d = d0 + dl;
    float u1 = 0.f, u2 = 0.f, u3 = 0.f;
#pragma unroll
    for (int i = 0; i < 8; i++) {
        int bc = b * NCH + cs * 8 + i;
        u1 += g_PU[(bc * 3 + 0) * Dn + d];
        u2 += g_PU[(bc * 3 + 1) * Dn + d];
        u3 += g_PU[(bc * 3 + 2) * Dn + d];
    }
    sred[cs * 64 + dl] = u1;
    sred[512 + cs * 64 + dl] = u2;
    sred[1024 + cs * 64 + dl] = u3;
    __syncthreads();
    if (t < 64) {
        float s1 = 0.f, s2 = 0.f, s3 = 0.f;
#pragma unroll
        for (int c = 0; c < 8; c++) {
            s1 += sred[c * 64 + t];
            s2 += sred[512 + c * 64 + t];
            s3 += sred[1024 + c * 64 + t];
        }
        g_U1[b * Dn + d0 + t] = s1;
        g_U2[b * Dn + d0 + t] = s2;
        g_U3[b * Dn + d0 + t] = s3;
    }
}

// ---------------- 2. per batch: batch mean/std, q, p ----------------
__global__ void k_qp(const float* __restrict__ wk, const float* __restrict__ wq,
                     const float* __restrict__ ln_g, const float* __restrict__ ln_b) {
    int b = blockIdx.x;
    int t = threadIdx.x;  // 256
    int w = t >> 5, lane = t & 31;
    __shared__ float ms[2 * Dn];
    __shared__ float qv[DKn];
    __shared__ float s_sc[2];

    float U1 = g_U1[b * Dn + t];
    float U2 = g_U2[b * Dn + t];
    float U3 = g_U3[b * Dn + t];
    if (w == 0) {
        float a = g_Psmr[b * NCH + lane] + g_Psmr[b * NCH + 32 + lane];
        a = warpSum(a);
        if (lane == 0) s_sc[0] = a;
    } else if (w == 1) {
        float a = g_Ps22[b * NCH + lane] + g_Ps22[b * NCH + 32 + lane];
        a = warpSum(a);
        if (lane == 0) s_sc[1] = a;
    }
    __syncthreads();
    float smr = s_sc[0], sm2r2 = s_sc[1];

    {
        int d = t;
        float g = ln_g[d], be = ln_b[d];
        float S1 = g * (U1 - smr) + (float)Ln * be;
        float S2 = g * g * (U2 - 2.0f * U3 + sm2r2) + 2.0f * g * be * (U1 - smr) + (float)Ln * be * be;
        float mean = S1 * (1.0f / Ln);
        float var = S2 * (1.0f / Ln) - mean * mean;
        float sd = sqrtf(fmaxf(var, EPS_CLIP));
        ms[d] = mean;
        ms[Dn + d] = sd;
    }
    __syncthreads();

#pragma unroll
    for (int i = 0; i < 16; i++) {
        int k = w * 16 + i;
        float acc = 0.f;
        const float* wr = wq + (size_t)k * 2 * Dn;
#pragma unroll
        for (int e = 0; e < 16; e++)
            acc = fmaf(wr[e * 32 + lane], ms[e * 32 + lane], acc);
        acc = warpSum(acc);
        if (lane == 0) qv[k] = acc;
    }
    __syncthreads();

    float p = 0.f;
#pragma unroll 8
    for (int k2 = 0; k2 < DKn; k2++) p = fmaf(wk[k2 * Dn + t], qv[k2], p);
    p *= rsqrtf((float)DKn);

    float gp = ln_g[t] * p;
    g_gp[b * Dn + t] = gp;
    float cb = bSum(ln_b[t] * p);
    float gpsum = bSum(gp);
    if (t == 0) { g_Cb[b] = cb; g_Gp[b] = gpsum; }
}

// ---------------- 3. FUSED scores + chunk softmax + weighted partials; phase B re-reads v ----------------
__global__ void __launch_bounds__(512, 3) k_fused(const float* __restrict__ v) {
    __shared__ float s_gp[Dn];
    __shared__ float s_mu[CH1], s_rs[CH1];
    __shared__ float s_c1[CH1], s_c2[CH1], s_c3[CH1];
    __shared__ float s_s[CH1];
    __shared__ float s_ml[1];
    __shared__ float sA[64 * 33];

    int t = threadIdx.x;                    // 512
    int b = (Bn - 1) - (blockIdx.x >> 6);   // reversed
    int ch = blockIdx.x & 63;
    int l0 = ch * CH1;
    int bc = b * NCH + ch;
    int dg = t >> 4;                        // 0..31
    int lv = t & 15;

    if (t < Dn) s_gp[t] = g_gp[b * Dn + t];
    if (t >= 256 && t < 320) s_mu[t - 256] = g_mu[b * Ln + l0 + (t - 256)];
    if (t >= 320 && t < 384) s_rs[t - 320] = g_rsig[b * Ln + l0 + (t - 320)];
    __syncthreads();

    const float* vbase = v + (size_t)b * Dn * Ln + l0 + lv * 4;
    float a0 = 0.f, a1 = 0.f, a2 = 0.f, a3 = 0.f;
#pragma unroll
    for (int it = 0; it < 8; it++) {
        int d = it * 32 + dg;
        float4 x = *reinterpret_cast<const float4*>(vbase + (size_t)d * Ln);
        float g = s_gp[d];
        a0 = fmaf(x.x, g, a0);
        a1 = fmaf(x.y, g, a1);
        a2 = fmaf(x.z, g, a2);
        a3 = fmaf(x.w, g, a3);
    }
    sA[(lv * 4 + 0) * 33 + dg] = a0;
    sA[(lv * 4 + 1) * 33 + dg] = a1;
    sA[(lv * 4 + 2) * 33 + dg] = a2;
    sA[(lv * 4 + 3) * 33 + dg] = a3;
    __syncthreads();

    if (t < CH1) {
        float dot = 0.f;
#pragma unroll
        for (int g = 0; g < 32; g++) dot += sA[t * 33 + g];
        s_s[t] = s_rs[t] * (dot - s_mu[t] * g_Gp[b]) + g_Cb[b];
    }
    __syncthreads();

    if (t < 32) {
        float m = fmaxf(s_s[t], s_s[32 + t]);
        m = warpMax(m);
        if (t == 0) { s_ml[0] = m; g_Pml[bc] = m; }
    }
    __syncthreads();

    if (t < CH1) {
        float e = __expf(s_s[t] - s_ml[0]);
        float rs = s_rs[t], mu = s_mu[t];
        float c1 = e * rs;
        float c2 = c1 * rs;
        s_c1[t] = c1;
        s_c2[t] = c2;
        s_c3[t] = c2 * mu;
        float mr = mu * rs;
        sA[t] = e;
        sA[64 + t] = e * mr;
        sA[128 + t] = e * mr * mr;
    }
    __syncthreads();
    if (t < 32) {
        float a = sA[t] + sA[32 + t];
        a = warpSum(a);
        if (t == 0) g_Pse[bc] = a;
    } else if (t < 64) {
        int u = t - 32;
        float a = sA[64 + u] + sA[96 + u];
        a = warpSum(a);
        if (u == 0) g_Pa[bc] = a;
    } else if (t < 96) {
        int u = t - 64;
        float a = sA[128 + u] + sA[160 + u];
        a = warpSum(a);
        if (u == 0) g_Pm2[bc] = a;
    }
    __syncthreads();

    float c10 = s_c1[lv * 4 + 0], c11 = s_c1[lv * 4 + 1], c12 = s_c1[lv * 4 + 2], c13 = s_c1[lv * 4 + 3];
    float c20 = s_c2[lv * 4 + 0], c21 = s_c2[lv * 4 + 1], c22 = s_c2[lv * 4 + 2], c23 = s_c2[lv * 4 + 3];
    float c30 = s_c3[lv * 4 + 0], c31 = s_c3[lv * 4 + 1], c32 = s_c3[lv * 4 + 2], c33 = s_c3[lv * 4 + 3];

    // Phase B: re-read v (L2-hot)
#pragma unroll
    for (int it = 0; it < 8; it++) {
        int d = it * 32 + dg;
        float4 xx = *reinterpret_cast<const float4*>(vbase + (size_t)d * Ln);
        float r1 = fmaf(xx.x, c10, fmaf(xx.y, c11, fmaf(xx.z, c12, xx.w * c13)));
        float r2 = fmaf(xx.x * xx.x, c20, fmaf(xx.y * xx.y, c21,
                   fmaf(xx.z * xx.z, c22, (xx.w * xx.w) * c23)));
        float r3 = fmaf(xx.x, c30, fmaf(xx.y, c31, fmaf(xx.z, c32, xx.w * c33)));
#pragma unroll
        for (int o = 8; o; o >>= 1) {
            r1 += __shfl_down_sync(0xffffffffu, r1, o);
            r2 += __shfl_down_sync(0xffffffffu, r2, o);
            r3 += __shfl_down_sync(0xffffffffu, r3, o);
        }
        if (lv == 0) {
            g_PR[(bc * 3 + 0) * Dn + d] = r1;
            g_PR[(bc * 3 + 1) * Dn + d] = r2;
            g_PR[(bc * 3 + 2) * Dn + d] = r3;
        }
    }
}

// ---------------- 3b. wide-grid flash-scaled combine of R partials ----------------
__global__ void __launch_bounds__(512) k_combineR() {
    __shared__ float sred[3 * 512];
    __shared__ float s_M[1];
    int b = blockIdx.x >> 2;
    int d0 = (blockIdx.x & 3) * 64;
    int t = threadIdx.x;
    int dl = t & 63, cs = t >> 6;
    int d = d0 + dl;

    if (t < 32) {
        float m = fmaxf(g_Pml[b * NCH + t], g_Pml[b * NCH + 32 + t]);
        m = warpMax(m);
        if (t == 0) s_M[0] = m;
    }
    __syncthreads();
    float M = s_M[0];

    float r1 = 0.f, r2 = 0.f, r3 = 0.f;
#pragma unroll
    for (int i = 0; i < 8; i++) {
        int c = cs * 8 + i;
        int bc = b * NCH + c;
        float sc = __expf(g_Pml[bc] - M);
        r1 = fmaf(g_PR[(bc * 3 + 0) * Dn + d], sc, r1);
        r2 = fmaf(g_PR[(bc * 3 + 1) * Dn + d], sc, r2);
        r3 = fmaf(g_PR[(bc * 3 + 2) * Dn + d], sc, r3);
    }
    sred[cs * 64 + dl] = r1;
    sred[512 + cs * 64 + dl] = r2;
    sred[1024 + cs * 64 + dl] = r3;
    __syncthreads();
    if (t < 64) {
        float s1 = 0.f, s2 = 0.f, s3 = 0.f;
#pragma unroll
        for (int c = 0; c < 8; c++) {
            s1 += sred[c * 64 + t];
            s2 += sred[512 + c * 64 + t];
            s3 += sred[1024 + c * 64 + t];
        }
        g_R1[b * Dn + d0 + t] = s1;
        g_R2[b * Dn + d0 + t] = s2;
        g_R3[b * Dn + d0 + t] = s3;
    }
}

// ---------------- 4. scalar flash combine + att stats -> corr + skip_conn ----------------
__global__ void __launch_bounds__(256) k_finalize(const float* __restrict__ fcq_w,
                                                  const float* __restrict__ fc_w,
                                                  const float* __restrict__ fc_b,
                                                  const float* __restrict__ ln_g,
                                                  const float* __restrict__ ln_b,
                                                  float* __restrict__ out) {
    int b = blockIdx.x;
    int t = threadIdx.x;  // 256
    int w = t >> 5, lane = t & 31;
    __shared__ float s_M[1];
    __shared__ float am[Dn], as[Dn];

    if (t < 32) {
        float m = fmaxf(g_Pml[b * NCH + t], g_Pml[b * NCH + 32 + t]);
        m = warpMax(m);
        if (t == 0) s_M[0] = m;
    }
    __syncthreads();
    float M = s_M[0];

    float sc = (t < NCH) ? __expf(g_Pml[b * NCH + t] - M) : 0.f;
    float se_p = (t < NCH) ? g_Pse[b * NCH + t] * sc : 0.f;
    float a_p  = (t < NCH) ? g_Pa[b * NCH + t] * sc : 0.f;
    float m2_p = (t < NCH) ? g_Pm2[b * NCH + t] * sc : 0.f;
    float SE = bSum(se_p);
    float Asum = bSum(a_p);
    float M2sum = bSum(m2_p);
    float inv = 1.0f / SE;
    float A = Asum * inv, M2 = M2sum * inv;

    {
        int d = t;
        float g = ln_g[d], be = ln_b[d];
        float R1 = g_R1[b * Dn + d] * inv;
        float R2 = g_R2[b * Dn + d] * inv;
        float R3 = g_R3[b * Dn + d] * inv;
        float mean = g * (R1 - A) + be;
        float E2 = g * g * (R2 - 2.0f * R3 + M2) + 2.0f * g * be * (R1 - A) + be * be;
        float var = E2 - mean * mean;
        am[d] = mean;
        as[d] = sqrtf(fmaxf(var, EPS_CLIP));
    }
    __syncthreads();

#pragma unroll
    for (int i = 0; i < 32; i++) {
        int o = w * 32 + i;
        const float* wr = fcq_w + (size_t)o * Dn;
        float c = 0.f;
#pragma unroll
        for (int e = 0; e < 8; e++)
            c = fmaf(wr[e * 32 + lane], am[e * 32 + lane], c);
        c = warpSum(c);

        const float* fr = fc_w + (size_t)o * 2 * Dn;
        float sk = 0.f;
#pragma unroll
        for (int e = 0; e < 8; e++) {
            sk = fmaf(fr[e * 32 + lane], am[e * 32 + lane], sk);
            sk = fmaf(fr[Dn + e * 32 + lane], as[e * 32 + lane], sk);
        }
        sk = warpSum(sk);

        if (lane == 0) {
            g_corr[b * Dn + o] = c;
            out[(size_t)Bn * Ln * Dn + b * Dn + o] = sk + fc_b[o];
        }
    }
}

// ---------------- 5. out1[b,l,o] = v[b,o,l] + corr[b,o]  (reversed batch order) ----------------
__global__ void k_out(const float* __restrict__ v, float* __restrict__ out) {
    __shared__ float tile[32 * 129];
    int b = (Bn - 1) - blockIdx.z;
    int l0 = blockIdx.x * 128;
    int o0 = blockIdx.y * 32;
    int tid = threadIdx.x;          // 256
    int w = tid >> 5, lane = tid & 31;

#pragma unroll
    for (int i = 0; i < 4; i++) {
        int ol = w + 8 * i;
        int o = o0 + ol;
        float c = g_corr[b * Dn + o];
        const float4* vr = reinterpret_cast<const float4*>(v + ((size_t)(b * Dn + o)) * Ln + l0);
        float4 x = __ldcs(vr + lane);
        tile[ol * 129 + lane * 4 + 0] = x.x + c;
        tile[ol * 129 + lane * 4 + 1] = x.y + c;
        tile[ol * 129 + lane * 4 + 2] = x.z + c;
        tile[ol * 129 + lane * 4 + 3] = x.w + c;
    }
    __syncthreads();

    int o4 = tid & 7;
    int lq = tid >> 3;
#pragma unroll
    for (int i = 0; i < 4; i++) {
        int l = i * 32 + lq;
        float4 y;
        y.x = tile[(o4 * 4 + 0) * 129 + l];
        y.y = tile[(o4 * 4 + 1) * 129 + l];
        y.z = tile[(o4 * 4 + 2) * 129 + l];
        y.w = tile[(o4 * 4 + 3) * 129 + l];
        __stcs(reinterpret_cast<float4*>(out + ((size_t)b * Ln + l0 + l) * Dn + o0 + o4 * 4), y);
    }
}

// ---------------- launcher ----------------
extern "C" void kernel_launch(void* const* d_in, const int* in_sizes, int n_in,
                              void* d_out, int out_size) {
    const float* v     = (const float*)d_in[0];
    const float* ln_g  = (const float*)d_in[1];
    const float* ln_b  = (const float*)d_in[2];
    const float* wk    = (const float*)d_in[3];
    const float* wq    = (const float*)d_in[4];
    const float* fcq_w = (const float*)d_in[5];
    const float* fc_w  = (const float*)d_in[6];
    const float* fc_b  = (const float*)d_in[7];
    float* out = (float*)d_out;

    k_pass1<<<Bn * NCH, 512>>>(v);
    k_combineU<<<Bn * 4, 512>>>();
    k_qp<<<Bn, 256>>>(wk, wq, ln_g, ln_b);
    k_fused<<<Bn * NCH, 512>>>(v);
    k_combineR<<<Bn * 4, 512>>>();
    k_finalize<<<Bn, 256>>>(fcq_w, fc_w, fc_b, ln_g, ln_b, out);
    k_out<<<dim3(Ln / 128, Dn / 32, Bn), 256>>>(v, out);
}

// round 15
// speedup vs baseline: 1.2547x; 1.2547x over previous
#include <cuda_runtime.h>
#include <cfloat>
#include <math.h>

#define Bn 64
#define Dn 256
#define Ln 4096
#define DKn 128
#define LN_EPS 1e-6f
#define EPS_CLIP 1e-10f

#define CH1 64                 // l-chunk per block
#define NCH (Ln / CH1)         // 64 chunks per batch

// ---------------- scratch (static device globals; no allocation) ----------------
__device__ float g_mu[Bn * Ln];
__device__ float g_rsig[Bn * Ln];
__device__ float g_PU[Bn * NCH * 3 * Dn];
__device__ float g_PR[Bn * NCH * 3 * Dn];
__device__ float g_Psmr[Bn * NCH];
__device__ float g_Ps22[Bn * NCH];
__device__ float g_Pml[Bn * NCH];
__device__ float g_Pse[Bn * NCH];
__device__ float g_Pa[Bn * NCH];
__device__ float g_Pm2[Bn * NCH];
__device__ float g_gp[Bn * Dn];
__device__ float g_corr[Bn * Dn];
__device__ float g_Cb[Bn], g_Gp[Bn];
__device__ unsigned int g_ctrU[Bn];   // zero-init; reset by elected block each run
__device__ unsigned int g_ctrR[Bn];

// ---------------- reduction helpers ----------------
__device__ __forceinline__ float warpSum(float v) {
#pragma unroll
    for (int o = 16; o; o >>= 1) v += __shfl_xor_sync(0xffffffffu, v, o);
    return v;
}
__device__ __forceinline__ float warpMax(float v) {
#pragma unroll
    for (int o = 16; o; o >>= 1) v = fmaxf(v, __shfl_xor_sync(0xffffffffu, v, o));
    return v;
}
__device__ __forceinline__ float bSum(float v) {
    __shared__ float sh[32];
    int lane = threadIdx.x & 31, w = threadIdx.x >> 5;
    int nw = (blockDim.x + 31) >> 5;
    v = warpSum(v);
    if (lane == 0) sh[w] = v;
    __syncthreads();
    if (w == 0) {
        float x = (lane < nw) ? sh[lane] : 0.0f;
        x = warpSum(x);
        if (lane == 0) sh[0] = x;
    }
    __syncthreads();
    float r = sh[0];
    __syncthreads();
    return r;
}

// ---------------- 1. LN stats + U-partials + (last block per batch) combineU + qp ----------------
__global__ void __launch_bounds__(512, 2) k_pass1(const float* __restrict__ v,
                                                  const float* __restrict__ wk,
                                                  const float* __restrict__ wq,
                                                  const float* __restrict__ ln_g,
                                                  const float* __restrict__ ln_b) {
    __shared__ float s_mu[CH1], s_rs[CH1], s_mr[CH1], s_m2[CH1];
    __shared__ float sA[64 * 33];
    __shared__ float sQ[64 * 33];
    __shared__ unsigned int s_ticket;

    int t = threadIdx.x;                    // 512
    int b = blockIdx.x >> 6;                // NCH == 64
    int ch = blockIdx.x & 63;
    int l0 = ch * CH1;
    int bc = blockIdx.x;
    int dg = t >> 4;                        // 0..31
    int lv = t & 15;

    const float* vbase = v + (size_t)b * Dn * Ln + l0 + lv * 4;
    float cs0 = 0.f, cs1 = 0.f, cs2 = 0.f, cs3 = 0.f;
    float cq0 = 0.f, cq1 = 0.f, cq2 = 0.f, cq3 = 0.f;
#pragma unroll
    for (int it = 0; it < 8; it++) {
        int d = it * 32 + dg;
        float4 x = *reinterpret_cast<const float4*>(vbase + (size_t)d * Ln);
        cs0 += x.x; cs1 += x.y; cs2 += x.z; cs3 += x.w;
        cq0 = fmaf(x.x, x.x, cq0);
        cq1 = fmaf(x.y, x.y, cq1);
        cq2 = fmaf(x.z, x.z, cq2);
        cq3 = fmaf(x.w, x.w, cq3);
    }
    sA[(lv * 4 + 0) * 33 + dg] = cs0;
    sA[(lv * 4 + 1) * 33 + dg] = cs1;
    sA[(lv * 4 + 2) * 33 + dg] = cs2;
    sA[(lv * 4 + 3) * 33 + dg] = cs3;
    sQ[(lv * 4 + 0) * 33 + dg] = cq0;
    sQ[(lv * 4 + 1) * 33 + dg] = cq1;
    sQ[(lv * 4 + 2) * 33 + dg] = cq2;
    sQ[(lv * 4 + 3) * 33 + dg] = cq3;
    __syncthreads();

    if (t < CH1) {
        float ss = 0.f, qq = 0.f;
#pragma unroll
        for (int g = 0; g < 32; g++) {
            ss += sA[t * 33 + g];
            qq += sQ[t * 33 + g];
        }
        float mu = ss * (1.0f / Dn);
        float var = qq * (1.0f / Dn) - mu * mu;
        float rs = rsqrtf(var + LN_EPS);
        s_mu[t] = mu;
        s_rs[t] = rs;
        g_mu[b * Ln + l0 + t] = mu;
        g_rsig[b * Ln + l0 + t] = rs;
        float mr = mu * rs;
        s_mr[t] = mr;
        s_m2[t] = mr * mr;
    }
    __syncthreads();

    if (t < 32) {
        float a = s_mr[t] + s_mr[32 + t];
        a = warpSum(a);
        if (t == 0) g_Psmr[bc] = a;
    } else if (t < 64) {
        int u = t - 32;
        float a = s_m2[u] + s_m2[32 + u];
        a = warpSum(a);
        if (u == 0) g_Ps22[bc] = a;
    }

    float r0 = s_rs[lv * 4 + 0], r1 = s_rs[lv * 4 + 1], r2 = s_rs[lv * 4 + 2], r3 = s_rs[lv * 4 + 3];
    float am0 = s_mu[lv * 4 + 0] * r0 * r0;
    float am1 = s_mu[lv * 4 + 1] * r1 * r1;
    float am2 = s_mu[lv * 4 + 2] * r2 * r2;
    float am3 = s_mu[lv * 4 + 3] * r3 * r3;

    // Phase B: re-read v (L2-hot)
#pragma unroll
    for (int it = 0; it < 8; it++) {
        int d = it * 32 + dg;
        float4 xx = *reinterpret_cast<const float4*>(vbase + (size_t)d * Ln);
        float xr0 = xx.x * r0, xr1 = xx.y * r1, xr2 = xx.z * r2, xr3 = xx.w * r3;
        float u1 = (xr0 + xr1) + (xr2 + xr3);
        float u2 = fmaf(xr0, xr0, fmaf(xr1, xr1, fmaf(xr2, xr2, xr3 * xr3)));
        float u3 = fmaf(xx.x, am0, fmaf(xx.y, am1, fmaf(xx.z, am2, xx.w * am3)));
#pragma unroll
        for (int o = 8; o; o >>= 1) {
            u1 += __shfl_down_sync(0xffffffffu, u1, o);
            u2 += __shfl_down_sync(0xffffffffu, u2, o);
            u3 += __shfl_down_sync(0xffffffffu, u3, o);
        }
        if (lv == 0) {
            g_PU[(bc * 3 + 0) * Dn + d] = u1;
            g_PU[(bc * 3 + 1) * Dn + d] = u2;
            g_PU[(bc * 3 + 2) * Dn + d] = u3;
        }
    }

    // ---- tail: last block of batch b performs combineU + qp ----
    __threadfence();
    if (t == 0) s_ticket = atomicAdd(&g_ctrU[b], 1u);
    __syncthreads();
    if (s_ticket != NCH - 1) return;
    if (t == 0) g_ctrU[b] = 0u;       // reset for next graph replay
    __threadfence();

    float* ms = sA;                   // [512] mean|sd
    float* qv = sQ;                   // [128]

    // combine U over chunks (t < 256, coalesced over d)
    float U1 = 0.f, U2 = 0.f, U3 = 0.f;
    if (t < Dn) {
#pragma unroll 8
        for (int c = 0; c < NCH; c++) {
            int bb = (b * NCH + c) * 3;
            U1 += g_PU[(bb + 0) * Dn + t];
            U2 += g_PU[(bb + 1) * Dn + t];
            U3 += g_PU[(bb + 2) * Dn + t];
        }
    }
    float smr_p = (t >= 256 && t < 320) ? g_Psmr[b * NCH + (t - 256)] : 0.f;
    float s22_p = (t >= 320 && t < 384) ? g_Ps22[b * NCH + (t - 320)] : 0.f;
    float smr = bSum(smr_p);
    float sm2r2 = bSum(s22_p);

    if (t < Dn) {
        float g = ln_g[t], be = ln_b[t];
        float S1 = g * (U1 - smr) + (float)Ln * be;
        float S2 = g * g * (U2 - 2.0f * U3 + sm2r2) + 2.0f * g * be * (U1 - smr) + (float)Ln * be * be;
        float mean = S1 * (1.0f / Ln);
        float var = S2 * (1.0f / Ln) - mean * mean;
        float sd = sqrtf(fmaxf(var, EPS_CLIP));
        ms[t] = mean;
        ms[Dn + t] = sd;
    }
    __syncthreads();

    int w = t >> 5, lane = t & 31;
    if (t < Dn) {   // warps 0..7: q = wq @ [mean; std]
#pragma unroll
        for (int i = 0; i < 16; i++) {
            int k = w * 16 + i;
            float acc = 0.f;
            const float* wr = wq + (size_t)k * 2 * Dn;
#pragma unroll
            for (int e = 0; e < 16; e++)
                acc = fmaf(wr[e * 32 + lane], ms[e * 32 + lane], acc);
            acc = warpSum(acc);
            if (lane == 0) qv[k] = acc;
        }
    }
    __syncthreads();

    float p = 0.f, gp = 0.f, cbv = 0.f;
    if (t < Dn) {
#pragma unroll 8
        for (int k2 = 0; k2 < DKn; k2++) p = fmaf(wk[k2 * Dn + t], qv[k2], p);
        p *= rsqrtf((float)DKn);
        gp = ln_g[t] * p;
        g_gp[b * Dn + t] = gp;
        cbv = ln_b[t] * p;
    }
    float cb = bSum(cbv);
    float gpsum = bSum(gp);
    if (t == 0) { g_Cb[b] = cb; g_Gp[b] = gpsum; }
}

// ---------------- 2. FUSED scores + chunk softmax + R-partials + (last block) combineR + finalize ----------------
__global__ void __launch_bounds__(512, 2) k_fused(const float* __restrict__ v,
                                                   const float* __restrict__ fcq_w,
                                                   const float* __restrict__ fc_w,
                                                   const float* __restrict__ fc_b,
                                                   const float* __restrict__ ln_g,
                                                   const float* __restrict__ ln_b,
                                                   float* __restrict__ out) {
    __shared__ float s_gp[Dn];
    __shared__ float s_mu[CH1], s_rs[CH1];
    __shared__ float s_c1[CH1], s_c2[CH1], s_c3[CH1];
    __shared__ float s_s[CH1];
    __shared__ float s_ml[1];
    __shared__ float sA[64 * 33];
    __shared__ unsigned int s_ticket;

    int t = threadIdx.x;                    // 512
    int b = (Bn - 1) - (blockIdx.x >> 6);   // reversed (L2 warmth after pass1)
    int ch = blockIdx.x & 63;
    int l0 = ch * CH1;
    int bc = b * NCH + ch;
    int dg = t >> 4;                        // 0..31
    int lv = t & 15;

    if (t < Dn) s_gp[t] = g_gp[b * Dn + t];
    if (t >= 256 && t < 320) s_mu[t - 256] = g_mu[b * Ln + l0 + (t - 256)];
    if (t >= 320 && t < 384) s_rs[t - 320] = g_rsig[b * Ln + l0 + (t - 320)];
    __syncthreads();

    const float* vbase = v + (size_t)b * Dn * Ln + l0 + lv * 4;
    float a0 = 0.f, a1 = 0.f, a2 = 0.f, a3 = 0.f;
#pragma unroll
    for (int it = 0; it < 8; it++) {
        int d = it * 32 + dg;
        float4 x = *reinterpret_cast<const float4*>(vbase + (size_t)d * Ln);
        float g = s_gp[d];
        a0 = fmaf(x.x, g, a0);
        a1 = fmaf(x.y, g, a1);
        a2 = fmaf(x.z, g, a2);
        a3 = fmaf(x.w, g, a3);
    }
    sA[(lv * 4 + 0) * 33 + dg] = a0;
    sA[(lv * 4 + 1) * 33 + dg] = a1;
    sA[(lv * 4 + 2) * 33 + dg] = a2;
    sA[(lv * 4 + 3) * 33 + dg] = a3;
    __syncthreads();

    if (t < CH1) {
        float dot = 0.f;
#pragma unroll
        for (int g = 0; g < 32; g++) dot += sA[t * 33 + g];
        s_s[t] = s_rs[t] * (dot - s_mu[t] * g_Gp[b]) + g_Cb[b];
    }
    __syncthreads();

    if (t < 32) {
        float m = fmaxf(s_s[t], s_s[32 + t]);
        m = warpMax(m);
        if (t == 0) { s_ml[0] = m; g_Pml[bc] = m; }
    }
    __syncthreads();

    if (t < CH1) {
        float e = __expf(s_s[t] - s_ml[0]);
        float rs = s_rs[t], mu = s_mu[t];
        float c1 = e * rs;
        float c2 = c1 * rs;
        s_c1[t] = c1;
        s_c2[t] = c2;
        s_c3[t] = c2 * mu;
        float mr = mu * rs;
        sA[t] = e;
        sA[64 + t] = e * mr;
        sA[128 + t] = e * mr * mr;
    }
    __syncthreads();
    if (t < 32) {
        float a = sA[t] + sA[32 + t];
        a = warpSum(a);
        if (t == 0) g_Pse[bc] = a;
    } else if (t < 64) {
        int u = t - 32;
        float a = sA[64 + u] + sA[96 + u];
        a = warpSum(a);
        if (u == 0) g_Pa[bc] = a;
    } else if (t < 96) {
        int u = t - 64;
        float a = sA[128 + u] + sA[160 + u];
        a = warpSum(a);
        if (u == 0) g_Pm2[bc] = a;
    }
    __syncthreads();

    float c10 = s_c1[lv * 4 + 0], c11 = s_c1[lv * 4 + 1], c12 = s_c1[lv * 4 + 2], c13 = s_c1[lv * 4 + 3];
    float c20 = s_c2[lv * 4 + 0], c21 = s_c2[lv * 4 + 1], c22 = s_c2[lv * 4 + 2], c23 = s_c2[lv * 4 + 3];
    float c30 = s_c3[lv * 4 + 0], c31 = s_c3[lv * 4 + 1], c32 = s_c3[lv * 4 + 2], c33 = s_c3[lv * 4 + 3];

#pragma unroll
    for (int it = 0; it < 8; it++) {
        int d = it * 32 + dg;
        float4 xx = *reinterpret_cast<const float4*>(vbase + (size_t)d * Ln);
        float r1 = fmaf(xx.x, c10, fmaf(xx.y, c11, fmaf(xx.z, c12, xx.w * c13)));
        float r2 = fmaf(xx.x * xx.x, c20, fmaf(xx.y * xx.y, c21,
                   fmaf(xx.z * xx.z, c22, (xx.w * xx.w) * c23)));
        float r3 = fmaf(xx.x, c30, fmaf(xx.y, c31, fmaf(xx.z, c32, xx.w * c33)));
#pragma unroll
        for (int o = 8; o; o >>= 1) {
            r1 += __shfl_down_sync(0xffffffffu, r1, o);
            r2 += __shfl_down_sync(0xffffffffu, r2, o);
            r3 += __shfl_down_sync(0xffffffffu, r3, o);
        }
        if (lv == 0) {
            g_PR[(bc * 3 + 0) * Dn + d] = r1;
            g_PR[(bc * 3 + 1) * Dn + d] = r2;
            g_PR[(bc * 3 + 2) * Dn + d] = r3;
        }
    }

    // ---- tail: last block of batch b performs combineR + finalize ----
    __threadfence();
    if (t == 0) s_ticket = atomicAdd(&g_ctrR[b], 1u);
    __syncthreads();
    if (s_ticket != NCH - 1) return;
    if (t == 0) g_ctrR[b] = 0u;
    __threadfence();

    int w = t >> 5, lane = t & 31;
    // global max over chunk maxima
    if (t < 32) {
        float m = fmaxf(g_Pml[b * NCH + t], g_Pml[b * NCH + 32 + t]);
        m = warpMax(m);
        if (t == 0) s_ml[0] = m;
    }
    __syncthreads();
    float M = s_ml[0];
    if (t < NCH) s_c1[t] = __expf(g_Pml[b * NCH + t] - M);   // reuse s_c1 as scale[64]
    __syncthreads();

    float R1 = 0.f, R2 = 0.f, R3 = 0.f;
    if (t < Dn) {
#pragma unroll 8
        for (int c = 0; c < NCH; c++) {
            int bb = (b * NCH + c) * 3;
            float sc = s_c1[c];
            R1 = fmaf(g_PR[(bb + 0) * Dn + t], sc, R1);
            R2 = fmaf(g_PR[(bb + 1) * Dn + t], sc, R2);
            R3 = fmaf(g_PR[(bb + 2) * Dn + t], sc, R3);
        }
    }
    float se_p = (t >= 256 && t < 320) ? g_Pse[b * NCH + (t - 256)] * s_c1[t - 256] : 0.f;
    float a_p  = (t >= 320 && t < 384) ? g_Pa[b * NCH + (t - 320)] * s_c1[t - 320] : 0.f;
    float m2_p = (t >= 384 && t < 448) ? g_Pm2[b * NCH + (t - 384)] * s_c1[t - 384] : 0.f;
    float SE = bSum(se_p);
    float Asum = bSum(a_p);
    float M2sum = bSum(m2_p);
    float inv = 1.0f / SE;
    float A = Asum * inv, M2 = M2sum * inv;

    float* am = sA;          // [256]
    float* as = sA + Dn;     // [256]
    if (t < Dn) {
        float g = ln_g[t], be = ln_b[t];
        R1 *= inv; R2 *= inv; R3 *= inv;
        float mean = g * (R1 - A) + be;
        float E2 = g * g * (R2 - 2.0f * R3 + M2) + 2.0f * g * be * (R1 - A) + be * be;
        float var = E2 - mean * mean;
        am[t] = mean;
        as[t] = sqrtf(fmaxf(var, EPS_CLIP));
    }
    __syncthreads();

    if (t < Dn) {   // warps 0..7, 32 outputs each
#pragma unroll
        for (int i = 0; i < 32; i++) {
            int o = w * 32 + i;
            const float* wr = fcq_w + (size_t)o * Dn;
            float c = 0.f;
#pragma unroll
            for (int e = 0; e < 8; e++)
                c = fmaf(wr[e * 32 + lane], am[e * 32 + lane], c);
            c = warpSum(c);

            const float* fr = fc_w + (size_t)o * 2 * Dn;
            float sk = 0.f;
#pragma unroll
            for (int e = 0; e < 8; e++) {
                sk = fmaf(fr[e * 32 + lane], am[e * 32 + lane], sk);
                sk = fmaf(fr[Dn + e * 32 + lane], as[e * 32 + lane], sk);
            }
            sk = warpSum(sk);

            if (lane == 0) {
                g_corr[b * Dn + o] = c;
                out[(size_t)Bn * Ln * Dn + b * Dn + o] = sk + fc_b[o];
            }
        }
    }
}

// ---------------- 3. out1[b,l,o] = v[b,o,l] + corr[b,o] ----------------
__global__ void k_out(const float* __restrict__ v, float* __restrict__ out) {
    __shared__ float tile[32 * 129];
    int b = (Bn - 1) - blockIdx.z;
    int l0 = blockIdx.x * 128;
    int o0 = blockIdx.y * 32;
    int tid = threadIdx.x;          // 256
    int w = tid >> 5, lane = tid & 31;

#pragma unroll
    for (int i = 0; i < 4; i++) {
        int ol = w + 8 * i;
        int o = o0 + ol;
        float c = g_corr[b * Dn + o];
        const float4* vr = reinterpret_cast<const float4*>(v + ((size_t)(b * Dn + o)) * Ln + l0);
        float4 x = __ldcs(vr + lane);
        tile[ol * 129 + lane * 4 + 0] = x.x + c;
        tile[ol * 129 + lane * 4 + 1] = x.y + c;
        tile[ol * 129 + lane * 4 + 2] = x.z + c;
        tile[ol * 129 + lane * 4 + 3] = x.w + c;
    }
    __syncthreads();

    int o4 = tid & 7;
    int lq = tid >> 3;
#pragma unroll
    for (int i = 0; i < 4; i++) {
        int l = i * 32 + lq;
        float4 y;
        y.x = tile[(o4 * 4 + 0) * 129 + l];
        y.y = tile[(o4 * 4 + 1) * 129 + l];
        y.z = tile[(o4 * 4 + 2) * 129 + l];
        y.w = tile[(o4 * 4 + 3) * 129 + l];
        __stcs(reinterpret_cast<float4*>(out + ((size_t)b * Ln + l0 + l) * Dn + o0 + o4 * 4), y);
    }
}

// ---------------- launcher: 3-kernel chain ----------------
extern "C" void kernel_launch(void* const* d_in, const int* in_sizes, int n_in,
                              void* d_out, int out_size) {
    const float* v     = (const float*)d_in[0];
    const float* ln_g  = (const float*)d_in[1];
    const float* ln_b  = (const float*)d_in[2];
    const float* wk    = (const float*)d_in[3];
    const float* wq    = (const float*)d_in[4];
    const float* fcq_w = (const float*)d_in[5];
    const float* fc_w  = (const float*)d_in[6];
    const float* fc_b  = (const float*)d_in[7];
    float* out = (float*)d_out;

    k_pass1<<<Bn * NCH, 512>>>(v, wk, wq, ln_g, ln_b);
    k_fused<<<Bn * NCH, 512>>>(v, fcq_w, fc_w, fc_b, ln_g, ln_b, out);
    k_out<<<dim3(Ln / 128, Dn / 32, Bn), 256>>>(v, out);
}